// round 9
// baseline (speedup 1.0000x reference)
#include <cuda_runtime.h>
#include <cuda_fp16.h>
#include <math.h>
#include <stdint.h>

// ---------------------------------------------------------------------------
// AuxLossFreeGate: scores = sigmoid(x @ W^T), group-limited top-k gate.
// GEMM: fp16 mma.sync, 2-way RN split (v = v1 + v2*2^-12), 3 product planes.
// All 8 warps compute; producer work (cp.async B from pre-split W image,
// LDG+split+STS for A) is interleaved INTO the MMA stream of each chunk,
// one __syncthreads per chunk, double-buffered SMEM.
// ---------------------------------------------------------------------------

#define N_EXPERTS   256
#define DIM_K       2048
#define N_GROUPS    8
#define TOPK        8
#define TOPK_GROUPS 4
#define ROUTE_SCALE 2.5f
#define MAX_T       32768
#define NEG_INF_F   (-1e30f)

__device__ float g_scores[(size_t)MAX_T * N_EXPERTS];

// ---------------- GEMM config ----------------
#define KC      32
#define NCHUNK  (DIM_K / KC)
#define ABLK    144
#define APLANE  (16 * ABLK)              // 2304 u32 per A plane
#define BBLK    66
#define BPLANE  (32 * BBLK)              // 2112 u32 per B plane
#define SB_OFF  (2 * APLANE)             // 4608
#define BCHUNK  (2 * BPLANE)             // 4224 u32 per (nh, chunk)
#define SMEM_U32 (SB_OFF + BCHUNK)       // 8832 u32 per buffer
#define SMEM_BYTES (2 * SMEM_U32 * 4)    // ~69 KB double buffered

// W image: [nh(2)][chunk(64)][plane(2)][2112], exact SMEM B layout.
__device__ __align__(16) uint32_t g_wimg[2 * NCHUNK * BCHUNK];

#define MMA_F16(d, a, b) asm volatile( \
    "mma.sync.aligned.m16n8k16.row.col.f32.f16.f16.f32 " \
    "{%0,%1,%2,%3},{%4,%5,%6,%7},{%8,%9},{%0,%1,%2,%3};" \
    : "+f"((d)[0]), "+f"((d)[1]), "+f"((d)[2]), "+f"((d)[3]) \
    : "r"((a).x), "r"((a).y), "r"((a).z), "r"((a).w), "r"((b).x), "r"((b).y))

#define CP_ASYNC16(dst_u32, src_ptr) \
    asm volatile("cp.async.cg.shared.global [%0], [%1], 16;" \
                 :: "r"(dst_u32), "l"(src_ptr) : "memory")
#define CP_COMMIT()  asm volatile("cp.async.commit_group;" ::: "memory")
#define CP_WAIT0()   asm volatile("cp.async.wait_group 0;" ::: "memory")

__device__ __forceinline__ uint32_t smem_to_u32(const void* p) {
    uint32_t a;
    asm("{ .reg .u64 t; cvta.to.shared.u64 t, %1; cvt.u32.u64 %0, t; }" : "=r"(a) : "l"(p));
    return a;
}

// 2-way fp16 split of 4 floats, pairwise packed (even k in lo half).
__device__ __forceinline__ void hsplit4(float4 v, uint32_t p1[2], uint32_t p2[2])
{
    __half2 a1 = __floats2half2_rn(v.x, v.y);
    __half2 b1 = __floats2half2_rn(v.z, v.w);
    p1[0] = *(uint32_t*)&a1;
    p1[1] = *(uint32_t*)&b1;
    float rx = (v.x - __half2float(__low2half(a1)))  * 4096.0f;
    float ry = (v.y - __half2float(__high2half(a1))) * 4096.0f;
    float rz = (v.z - __half2float(__low2half(b1)))  * 4096.0f;
    float rw = (v.w - __half2float(__high2half(b1))) * 4096.0f;
    __half2 a2 = __floats2half2_rn(rx, ry);
    __half2 b2 = __floats2half2_rn(rz, rw);
    p2[0] = *(uint32_t*)&a2;
    p2[1] = *(uint32_t*)&b2;
}

__device__ __forceinline__ float sigf(float v) { return 1.0f / (1.0f + expf(-v)); }

// ---------------------------------------------------------------------------
// Kernel 0: pre-split W into fragment-image layout (validated round 7).
// ---------------------------------------------------------------------------
__global__ __launch_bounds__(256)
void wsplit_kernel(const float* __restrict__ W)
{
    const int gid = blockIdx.x * 256 + threadIdx.x;
    const int n = gid >> 10;
    const int p = gid & 1023;
    const int k = 2 * p;

    float2 w = *(const float2*)(W + (size_t)n * DIM_K + k);
    uint32_t p1[2], p2[2];
    hsplit4(make_float4(w.x, w.y, 0.f, 0.f), p1, p2);

    const int nh = n >> 7;
    const int nl = n & 127;
    const int nt = nl >> 3;
    const int cn = nl & 7;
    const int c  = k >> 5;
    const int kk = k & 31;
    const int ks = kk >> 4;
    const int kb = kk & 15;
    const int slot = cn * 4 + ((kb >> 1) & 3);
    const int reg  = kb >> 3;

    const int base = (nh * NCHUNK + c) * BCHUNK + (nt * 2 + ks) * BBLK + slot * 2 + reg;
    g_wimg[base]          = p1[0];
    g_wimg[base + BPLANE] = p2[0];
}

// ---------------------------------------------------------------------------
// Kernel 1: GEMM. CTA = 128 tokens x 128 experts, 8 warps (4M x 2N).
// ---------------------------------------------------------------------------
__global__ __launch_bounds__(256)
void gemm_hmma_kernel(const float* __restrict__ X)
{
    extern __shared__ uint32_t sm[];
    const uint32_t smem_base = smem_to_u32(sm);
    const int tid  = threadIdx.x;
    const int warp = tid >> 5;
    const int lane = tid & 31;

    const int mt_blk = blockIdx.x >> 1;
    const int nh     = blockIdx.x & 1;

    const float* xb = X + (size_t)mt_blk * 128 * DIM_K;
    const uint32_t* wimg = g_wimg + (size_t)nh * NCHUNK * BCHUNK;

    // A loader geometry (validated round 6/7): idx = tid + j*256
    int goff[4], aad[4];
#pragma unroll
    for (int j = 0; j < 4; ++j) {
        const int idx = tid + j * 256;
        const int row = idx >> 3;
        const int c4  = (idx & 7) * 4;
        goff[j] = row * DIM_K + c4;
        const int ks = c4 >> 4;
        const int kb = c4 & 15;
        const int tc = (kb >> 1) & 3;
        const int mt = row >> 4, r = row & 15;
        const int slot = (r & 7) * 4 + tc;
        const int reg  = (r >> 3) + 2 * ((kb >> 3) & 1);
        aad[j] = (mt * 2 + ks) * ABLK + slot * 4 + (slot >> 3) * 4 + reg;
    }

    float accM[2][8][4], accS[2][8][4];
#pragma unroll
    for (int mi = 0; mi < 2; ++mi)
#pragma unroll
        for (int ni = 0; ni < 8; ++ni)
#pragma unroll
            for (int q = 0; q < 4; ++q) { accM[mi][ni][q] = 0.f; accS[mi][ni][q] = 0.f; }

    const int wmt = (warp >> 1) * 2;
    const int wnt = (warp & 1) * 8;

    // ---- prologue: fill buffer 0 with chunk 0 (A via LDG+split, B via cp.async)
    {
        const uint32_t dstb = smem_base + SB_OFF * 4;
#pragma unroll
        for (int j = 0; j < 4; ++j) {
            const int idx = j * 256 + tid;
            CP_ASYNC16(dstb + idx * 16, wimg + idx * 4);
        }
        if (tid < 32) {
            const int idx = 1024 + tid;
            CP_ASYNC16(dstb + idx * 16, wimg + idx * 4);
        }
        CP_COMMIT();

#pragma unroll
        for (int j = 0; j < 4; ++j) {
            float4 v = *(const float4*)(xb + goff[j]);
            uint32_t p1[2], p2[2];
            hsplit4(v, p1, p2);
            sm[aad[j]]              = p1[0];
            sm[aad[j] + 4]          = p1[1];
            sm[aad[j] + APLANE]     = p2[0];
            sm[aad[j] + APLANE + 4] = p2[1];
        }
        CP_WAIT0();
        __syncthreads();
    }

    for (int c = 0; c < NCHUNK; ++c) {
        uint32_t* smb  = sm + (c & 1) * SMEM_U32;          // compute buffer
        uint32_t* nbuf = sm + ((c + 1) & 1) * SMEM_U32;    // fill buffer
        const bool more = (c + 1) < NCHUNK;

        // ---- issue B(c+1) cp.async + A(c+1) LDG (ride under compute) ----
        float4 ra[4];
        if (more) {
            const uint32_t* src = wimg + (c + 1) * BCHUNK;
            const uint32_t dstb = smem_base + (((c + 1) & 1) * SMEM_U32 + SB_OFF) * 4;
#pragma unroll
            for (int j = 0; j < 4; ++j) {
                const int idx = j * 256 + tid;
                CP_ASYNC16(dstb + idx * 16, src + idx * 4);
            }
            if (tid < 32) {
                const int idx = 1024 + tid;
                CP_ASYNC16(dstb + idx * 16, src + idx * 4);
            }
            const int k0 = (c + 1) * KC;
#pragma unroll
            for (int j = 0; j < 4; ++j)
                ra[j] = *(const float4*)(xb + goff[j] + k0);
        }
        CP_COMMIT();   // uniform group structure every iteration

        // ---- compute ks=0 on smb ----
#define COMPUTE_KS(KS_) \
        { \
            uint4 af[2][2]; \
            _Pragma("unroll") \
            for (int p = 0; p < 2; ++p) \
                _Pragma("unroll") \
                for (int mi = 0; mi < 2; ++mi) \
                    af[p][mi] = *(const uint4*)&smb[p * APLANE + \
                        ((wmt + mi) * 2 + (KS_)) * ABLK + lane * 4 + (lane >> 3) * 4]; \
            _Pragma("unroll") \
            for (int nq = 0; nq < 2; ++nq) { \
                const int nb = nq * 4; \
                uint2 bf[4][2]; \
                _Pragma("unroll") \
                for (int ni4 = 0; ni4 < 4; ++ni4) { \
                    const int bbase = ((wnt + nb + ni4) * 2 + (KS_)) * BBLK + lane * 2; \
                    _Pragma("unroll") \
                    for (int q = 0; q < 2; ++q) \
                        bf[ni4][q] = *(const uint2*)&smb[SB_OFF + q * BPLANE + bbase]; \
                } \
                _Pragma("unroll") \
                for (int ni4 = 0; ni4 < 4; ++ni4) { \
                    MMA_F16(accM[0][nb + ni4], af[0][0], bf[ni4][0]); \
                    MMA_F16(accM[1][nb + ni4], af[0][1], bf[ni4][0]); \
                } \
                _Pragma("unroll") \
                for (int ni4 = 0; ni4 < 4; ++ni4) { \
                    MMA_F16(accS[0][nb + ni4], af[0][0], bf[ni4][1]); \
                    MMA_F16(accS[1][nb + ni4], af[0][1], bf[ni4][1]); \
                } \
                _Pragma("unroll") \
                for (int ni4 = 0; ni4 < 4; ++ni4) { \
                    MMA_F16(accS[0][nb + ni4], af[1][0], bf[ni4][0]); \
                    MMA_F16(accS[1][nb + ni4], af[1][1], bf[ni4][0]); \
                } \
            } \
        }

        COMPUTE_KS(0)

        // ---- split + STS A(c+1) into nbuf (interleaves with MMA stream) ----
        if (more) {
#pragma unroll
            for (int j = 0; j < 4; ++j) {
                uint32_t p1[2], p2[2];
                hsplit4(ra[j], p1, p2);
                nbuf[aad[j]]              = p1[0];
                nbuf[aad[j] + 4]          = p1[1];
                nbuf[aad[j] + APLANE]     = p2[0];
                nbuf[aad[j] + APLANE + 4] = p2[1];
            }
        }

        // ---- compute ks=1 on smb ----
        COMPUTE_KS(1)
#undef COMPUTE_KS

        // ---- close the chunk: B(c+1) landed, all warps done with smb ----
        CP_WAIT0();
        __syncthreads();
    }

    // ---- epilogue: accM + accS*2^-12 -> sigmoid -> g_scores ----
    const float INV = 1.0f / 4096.0f;
    const int rbase = mt_blk * 128 + (warp >> 1) * 32 + (lane >> 2);
    const int cbase = nh * 128 + (warp & 1) * 64 + (lane & 3) * 2;
#pragma unroll
    for (int mi = 0; mi < 2; ++mi) {
#pragma unroll
        for (int ni = 0; ni < 8; ++ni) {
            const int rr = rbase + mi * 16;
            const int cc = cbase + ni * 8;
            float2 v0, v1;
            v0.x = sigf(fmaf(accS[mi][ni][0], INV, accM[mi][ni][0]));
            v0.y = sigf(fmaf(accS[mi][ni][1], INV, accM[mi][ni][1]));
            v1.x = sigf(fmaf(accS[mi][ni][2], INV, accM[mi][ni][2]));
            v1.y = sigf(fmaf(accS[mi][ni][3], INV, accM[mi][ni][3]));
            *(float2*)&g_scores[(size_t)rr * N_EXPERTS + cc] = v0;
            *(float2*)&g_scores[(size_t)(rr + 8) * N_EXPERTS + cc] = v1;
        }
    }
}

// ---------------------------------------------------------------------------
// Kernel 2: gating. One warp per token; lane owns experts [lane*8, lane*8+8).
// ---------------------------------------------------------------------------
__device__ __forceinline__ uint32_t fkey(float f) {
    uint32_t u = __float_as_uint(f);
    return u ^ (uint32_t)(((int32_t)u >> 31) | 0x80000000);
}

__global__ __launch_bounds__(256)
void gate_kernel(const float* __restrict__ bias,
                 float* __restrict__ out_w, float* __restrict__ out_i, int T)
{
    const int warp = threadIdx.x >> 5;
    const int lane = threadIdx.x & 31;
    const int t = blockIdx.x * 8 + warp;
    if (t >= T) return;

    const float* srow = g_scores + (size_t)t * N_EXPERTS;

    float s[8], b[8];
    {
        float4 s0 = *(const float4*)(srow + lane * 8);
        float4 s1 = *(const float4*)(srow + lane * 8 + 4);
        float4 b0 = *(const float4*)(bias + lane * 8);
        float4 b1 = *(const float4*)(bias + lane * 8 + 4);
        s[0]=s0.x; s[1]=s0.y; s[2]=s0.z; s[3]=s0.w;
        s[4]=s1.x; s[5]=s1.y; s[6]=s1.z; s[7]=s1.w;
        b[0]=s[0]+b0.x; b[1]=s[1]+b0.y; b[2]=s[2]+b0.z; b[3]=s[3]+b0.w;
        b[4]=s[4]+b1.x; b[5]=s[5]+b1.y; b[6]=s[6]+b1.z; b[7]=s[7]+b1.w;
    }

    float m1 = NEG_INF_F, m2 = NEG_INF_F;
#pragma unroll
    for (int j = 0; j < 8; ++j) {
        float v = b[j];
        if (v > m1) { m2 = m1; m1 = v; }
        else if (v > m2) { m2 = v; }
    }
#pragma unroll
    for (int off = 1; off <= 2; off <<= 1) {
        float o1 = __shfl_xor_sync(0xffffffffu, m1, off);
        float o2 = __shfl_xor_sync(0xffffffffu, m2, off);
        if (o1 > m1) { m2 = fmaxf(m1, o2); m1 = o1; }
        else         { m2 = fmaxf(m2, o1); }
    }
    const float gsc = m1 + m2;
    const int myg = lane >> 2;

    int rank = 0;
#pragma unroll
    for (int g2 = 0; g2 < N_GROUPS; ++g2) {
        float og = __shfl_sync(0xffffffffu, gsc, g2 * 4);
        rank += (og > gsc) || (og == gsc && g2 < myg);
    }
    const bool kept = rank < TOPK_GROUPS;

    uint32_t key[8];
#pragma unroll
    for (int j = 0; j < 8; ++j) key[j] = fkey(b[j]);
    uint32_t mask = kept ? 0xFFu : 0u;

    float topw[TOPK]; int topi[TOPK];
    float wsum = 0.f;
#pragma unroll
    for (int it = 0; it < TOPK; ++it) {
        uint32_t bk = 0; uint32_t be = 0x7fffffffu; float bs = 0.f;
#pragma unroll
        for (int j = 0; j < 8; ++j) {
            const bool live = (mask >> j) & 1u;
            if (live && key[j] > bk) { bk = key[j]; be = lane * 8 + j; bs = s[j]; }
        }
#pragma unroll
        for (int off = 16; off; off >>= 1) {
            uint32_t ok = __shfl_xor_sync(0xffffffffu, bk, off);
            uint32_t oe = __shfl_xor_sync(0xffffffffu, be, off);
            float    os = __shfl_xor_sync(0xffffffffu, bs, off);
            if (ok > bk || (ok == bk && oe < be)) { bk = ok; be = oe; bs = os; }
        }
        topw[it] = bs; topi[it] = (int)be; wsum += bs;
        if ((be >> 3) == (uint32_t)lane) mask &= ~(1u << (be & 7u));
    }

    const float scale = ROUTE_SCALE / fmaxf(wsum, 1e-10f);
    if (lane == 0) {
#pragma unroll
        for (int j = 0; j < TOPK; ++j) {
            out_w[(size_t)t * TOPK + j] = topw[j] * scale;
            out_i[(size_t)t * TOPK + j] = (float)topi[j];
        }
    }
}

// ---------------------------------------------------------------------------
extern "C" void kernel_launch(void* const* d_in, const int* in_sizes, int n_in,
                              void* d_out, int out_size)
{
    const float* x    = (const float*)d_in[0];
    const float* w    = (const float*)d_in[1];
    const float* bias = (const float*)d_in[2];

    int T = in_sizes[0] / DIM_K;
    if (T > MAX_T) T = MAX_T;

    float* out_w = (float*)d_out;
    float* out_i = (float*)d_out + (size_t)T * TOPK;

    wsplit_kernel<<<1024, 256>>>(w);

    cudaFuncSetAttribute(gemm_hmma_kernel,
                         cudaFuncAttributeMaxDynamicSharedMemorySize, SMEM_BYTES);
    gemm_hmma_kernel<<<(T / 128) * 2, 256, SMEM_BYTES>>>(x);

    gate_kernel<<<(T + 7) / 8, 256>>>(bias, out_w, out_i, T);
}

// round 10
// speedup vs baseline: 1.0920x; 1.0920x over previous
#include <cuda_runtime.h>
#include <cuda_fp16.h>
#include <math.h>
#include <stdint.h>

// ---------------------------------------------------------------------------
// AuxLossFreeGate, fully fused GEMM+gate:
//   CTA = 64 tokens x 256 experts (ALL experts -> gate can run in-CTA).
//   GEMM: fp16 mma.sync, 2-way RN split (v = v1 + v2*2^-12), 3 product planes
//   (round-6-validated numerics). B comes from a pre-split W image via
//   cp.async; A is LDG+split+STS inline (round-7-validated loop).
//   Epilogue: sigmoid scores -> SMEM, then warps gate 8 tokens each
//   (round-7-validated gate logic) and write weights+indices directly.
// ---------------------------------------------------------------------------

#define N_EXPERTS   256
#define DIM_K       2048
#define N_GROUPS    8
#define TOPK        8
#define TOPK_GROUPS 4
#define ROUTE_SCALE 2.5f
#define MAX_T       32768
#define NEG_INF_F   (-1e30f)

// ---------------- GEMM config ----------------
#define KC       32
#define NCHUNK   (DIM_K / KC)
#define ABLK     144
#define APLANE   (8 * ABLK)               // 1152 u32 per A plane (64 rows)
#define BBLK     66
#define BPLANE   (64 * BBLK)              // 4224 u32 per B plane (256 experts)
#define SB_OFF   (2 * APLANE)             // 2304
#define BCHUNK   (2 * BPLANE)             // 8448 u32 per chunk in W image
#define SMEM_U32 (SB_OFF + BCHUNK)        // 10752 u32 per buffer
#define SC_OFF   (2 * SMEM_U32)           // scores region after both buffers
#define SC_STRIDE 264                     // u32 per score row (16B-aligned rows)
#define SMEM_BYTES ((SC_OFF + 64 * SC_STRIDE) * 4)   // 153600 B

// W image: [chunk(64)][plane(2)][4224], exact SMEM B layout.
__device__ __align__(16) uint32_t g_wimg[NCHUNK * BCHUNK];

#define MMA_F16(d, a, b) asm volatile( \
    "mma.sync.aligned.m16n8k16.row.col.f32.f16.f16.f32 " \
    "{%0,%1,%2,%3},{%4,%5,%6,%7},{%8,%9},{%0,%1,%2,%3};" \
    : "+f"((d)[0]), "+f"((d)[1]), "+f"((d)[2]), "+f"((d)[3]) \
    : "r"((a).x), "r"((a).y), "r"((a).z), "r"((a).w), "r"((b).x), "r"((b).y))

#define CP_ASYNC16(dst_u32, src_ptr) \
    asm volatile("cp.async.cg.shared.global [%0], [%1], 16;" \
                 :: "r"(dst_u32), "l"(src_ptr) : "memory")
#define CP_COMMIT()  asm volatile("cp.async.commit_group;" ::: "memory")
#define CP_WAIT0()   asm volatile("cp.async.wait_group 0;" ::: "memory")

__device__ __forceinline__ uint32_t smem_to_u32(const void* p) {
    uint32_t a;
    asm("{ .reg .u64 t; cvta.to.shared.u64 t, %1; cvt.u32.u64 %0, t; }" : "=r"(a) : "l"(p));
    return a;
}

// 2-way fp16 split of 4 floats, pairwise packed (even k in lo half).
__device__ __forceinline__ void hsplit4(float4 v, uint32_t p1[2], uint32_t p2[2])
{
    __half2 a1 = __floats2half2_rn(v.x, v.y);
    __half2 b1 = __floats2half2_rn(v.z, v.w);
    p1[0] = *(uint32_t*)&a1;
    p1[1] = *(uint32_t*)&b1;
    float rx = (v.x - __half2float(__low2half(a1)))  * 4096.0f;
    float ry = (v.y - __half2float(__high2half(a1))) * 4096.0f;
    float rz = (v.z - __half2float(__low2half(b1)))  * 4096.0f;
    float rw = (v.w - __half2float(__high2half(b1))) * 4096.0f;
    __half2 a2 = __floats2half2_rn(rx, ry);
    __half2 b2 = __floats2half2_rn(rz, rw);
    p2[0] = *(uint32_t*)&a2;
    p2[1] = *(uint32_t*)&b2;
}

__device__ __forceinline__ float sigf(float v) { return 1.0f / (1.0f + expf(-v)); }

__device__ __forceinline__ uint32_t fkey(float f) {
    uint32_t u = __float_as_uint(f);
    return u ^ (uint32_t)(((int32_t)u >> 31) | 0x80000000);
}

// ---------------------------------------------------------------------------
// Kernel 0: pre-split W into fragment-image layout (round-7 math, single image)
// ---------------------------------------------------------------------------
__global__ __launch_bounds__(256)
void wsplit_kernel(const float* __restrict__ W)
{
    const int gid = blockIdx.x * 256 + threadIdx.x;   // 0..262143
    const int n = gid >> 10;                          // expert 0..255
    const int p = gid & 1023;                         // k-pair
    const int k = 2 * p;

    float2 w = *(const float2*)(W + (size_t)n * DIM_K + k);
    uint32_t p1[2], p2[2];
    hsplit4(make_float4(w.x, w.y, 0.f, 0.f), p1, p2);

    const int nt = n >> 3;
    const int cn = n & 7;
    const int c  = k >> 5;
    const int kk = k & 31;
    const int ks = kk >> 4;
    const int kb = kk & 15;
    const int slot = cn * 4 + ((kb >> 1) & 3);
    const int reg  = kb >> 3;

    const int base = c * BCHUNK + (nt * 2 + ks) * BBLK + slot * 2 + reg;
    g_wimg[base]          = p1[0];
    g_wimg[base + BPLANE] = p2[0];
}

// ---------------------------------------------------------------------------
// Kernel 1: fused GEMM + gate. CTA = 64 tokens x 256 experts, 8 warps.
// Warp grid 2(M) x 4(N): warp tile = 32 tokens x 64 experts.
// ---------------------------------------------------------------------------
__global__ __launch_bounds__(256)
void fused_kernel(const float* __restrict__ X, const float* __restrict__ bias,
                  float* __restrict__ out_w, float* __restrict__ out_i)
{
    extern __shared__ uint32_t sm[];
    const uint32_t smem_base = smem_to_u32(sm);
    const int tid  = threadIdx.x;
    const int warp = tid >> 5;
    const int lane = tid & 31;

    const int mt_blk = blockIdx.x;                  // 64-token tile
    const float* xb = X + (size_t)mt_blk * 64 * DIM_K;

    // A loader geometry: 512 float4 per chunk, 2 per thread
    int goff[2], aad[2];
#pragma unroll
    for (int j = 0; j < 2; ++j) {
        const int idx = tid + j * 256;
        const int row = idx >> 3;                   // 0..63
        const int c4  = (idx & 7) * 4;
        goff[j] = row * DIM_K + c4;
        const int ks = c4 >> 4;
        const int kb = c4 & 15;
        const int tc = (kb >> 1) & 3;
        const int mt = row >> 4, r = row & 15;
        const int slot = (r & 7) * 4 + tc;
        const int reg  = (r >> 3) + 2 * ((kb >> 3) & 1);
        aad[j] = (mt * 2 + ks) * ABLK + slot * 4 + (slot >> 3) * 4 + reg;
    }

    float accM[2][8][4], accS[2][8][4];
#pragma unroll
    for (int mi = 0; mi < 2; ++mi)
#pragma unroll
        for (int ni = 0; ni < 8; ++ni)
#pragma unroll
            for (int q = 0; q < 4; ++q) { accM[mi][ni][q] = 0.f; accS[mi][ni][q] = 0.f; }

    const int wmt = (warp >> 2) * 2;                // m-tile base (0 or 2)
    const int wnt = (warp & 3) * 8;                 // n-tile base (0,8,16,24)

    // ---- prologue: issue B(0) cp.async, load A(0) registers ----
    {
        const uint32_t dstb = smem_base + SB_OFF * 4;
#pragma unroll
        for (int j = 0; j < 8; ++j) {
            const int idx = j * 256 + tid;          // 0..2047 uint4
            CP_ASYNC16(dstb + idx * 16, g_wimg + idx * 4);
        }
        if (tid < 64) {
            const int idx = 2048 + tid;
            CP_ASYNC16(dstb + idx * 16, g_wimg + idx * 4);
        }
        CP_COMMIT();
    }
    float4 ra[2];
#pragma unroll
    for (int j = 0; j < 2; ++j) ra[j] = *(const float4*)(xb + goff[j]);

    for (int c = 0; c < NCHUNK; ++c) {
        uint32_t* smb = sm + (c & 1) * SMEM_U32;

        // ---- split + store A(c) (buffer last read at chunk c-2; safe) ----
#pragma unroll
        for (int j = 0; j < 2; ++j) {
            uint32_t p1[2], p2[2];
            hsplit4(ra[j], p1, p2);
            smb[aad[j]]              = p1[0];
            smb[aad[j] + 4]          = p1[1];
            smb[aad[j] + APLANE]     = p2[0];
            smb[aad[j] + APLANE + 4] = p2[1];
        }

        CP_WAIT0();                                  // B(c) landed
        __syncthreads();

        // ---- issue B(c+1) into the other buffer ----
        if (c + 1 < NCHUNK) {
            const uint32_t* src = g_wimg + (c + 1) * BCHUNK;
            const uint32_t dstb = smem_base + (((c + 1) & 1) * SMEM_U32 + SB_OFF) * 4;
#pragma unroll
            for (int j = 0; j < 8; ++j) {
                const int idx = j * 256 + tid;
                CP_ASYNC16(dstb + idx * 16, src + idx * 4);
            }
            if (tid < 64) {
                const int idx = 2048 + tid;
                CP_ASYNC16(dstb + idx * 16, src + idx * 4);
            }
        }
        CP_COMMIT();

        // ---- prefetch A(c+1) ----
        if (c + 1 < NCHUNK) {
            const int k0 = (c + 1) * KC;
#pragma unroll
            for (int j = 0; j < 2; ++j)
                ra[j] = *(const float4*)(xb + goff[j] + k0);
        }

        // ---- compute chunk c: 3 planes ----
#pragma unroll
        for (int ks = 0; ks < 2; ++ks) {
            uint4 af[2][2];
#pragma unroll
            for (int p = 0; p < 2; ++p)
#pragma unroll
                for (int mi = 0; mi < 2; ++mi)
                    af[p][mi] = *(const uint4*)&smb[p * APLANE +
                        ((wmt + mi) * 2 + ks) * ABLK + lane * 4 + (lane >> 3) * 4];

#pragma unroll
            for (int nq = 0; nq < 2; ++nq) {
                const int nb = nq * 4;
                uint2 bf[4][2];
#pragma unroll
                for (int ni4 = 0; ni4 < 4; ++ni4) {
                    const int bbase = ((wnt + nb + ni4) * 2 + ks) * BBLK + lane * 2;
#pragma unroll
                    for (int q = 0; q < 2; ++q)
                        bf[ni4][q] = *(const uint2*)&smb[SB_OFF + q * BPLANE + bbase];
                }
#define DO_TERM(DST, P_, Q_) \
                { \
                    _Pragma("unroll") \
                    for (int ni4 = 0; ni4 < 4; ++ni4) { \
                        MMA_F16(DST[0][nb + ni4], af[P_][0], bf[ni4][Q_]); \
                        MMA_F16(DST[1][nb + ni4], af[P_][1], bf[ni4][Q_]); \
                    } \
                }
                DO_TERM(accM, 0, 0)
                DO_TERM(accS, 0, 1)
                DO_TERM(accS, 1, 0)
#undef DO_TERM
            }
        }
    }

    // ---- epilogue 1: sigmoid scores -> SMEM (64 x 256, stride 264) ----
    __syncthreads();                                 // all buffers now reusable
    float* scs = (float*)(sm + SC_OFF);
    const float INV = 1.0f / 4096.0f;
    const int rbase = (warp >> 2) * 32 + (lane >> 2);
    const int cbase = (warp & 3) * 64 + (lane & 3) * 2;
#pragma unroll
    for (int mi = 0; mi < 2; ++mi) {
#pragma unroll
        for (int ni = 0; ni < 8; ++ni) {
            const int rr = rbase + mi * 16;
            const int cc = cbase + ni * 8;
            float2 v0, v1;
            v0.x = sigf(fmaf(accS[mi][ni][0], INV, accM[mi][ni][0]));
            v0.y = sigf(fmaf(accS[mi][ni][1], INV, accM[mi][ni][1]));
            v1.x = sigf(fmaf(accS[mi][ni][2], INV, accM[mi][ni][2]));
            v1.y = sigf(fmaf(accS[mi][ni][3], INV, accM[mi][ni][3]));
            *(float2*)&scs[rr * SC_STRIDE + cc] = v0;
            *(float2*)&scs[(rr + 8) * SC_STRIDE + cc] = v1;
        }
    }
    __syncthreads();

    // ---- epilogue 2: gate 8 tokens per warp (round-7-validated logic) ----
    float4 bb0 = *(const float4*)(bias + lane * 8);
    float4 bb1 = *(const float4*)(bias + lane * 8 + 4);

    for (int tt = 0; tt < 8; ++tt) {
        const int row = warp * 8 + tt;
        const float* srow = scs + row * SC_STRIDE;

        float s[8], b[8];
        {
            float4 s0 = *(const float4*)(srow + lane * 8);
            float4 s1 = *(const float4*)(srow + lane * 8 + 4);
            s[0]=s0.x; s[1]=s0.y; s[2]=s0.z; s[3]=s0.w;
            s[4]=s1.x; s[5]=s1.y; s[6]=s1.z; s[7]=s1.w;
            b[0]=s[0]+bb0.x; b[1]=s[1]+bb0.y; b[2]=s[2]+bb0.z; b[3]=s[3]+bb0.w;
            b[4]=s[4]+bb1.x; b[5]=s[5]+bb1.y; b[6]=s[6]+bb1.z; b[7]=s[7]+bb1.w;
        }

        float m1 = NEG_INF_F, m2 = NEG_INF_F;
#pragma unroll
        for (int j = 0; j < 8; ++j) {
            float v = b[j];
            if (v > m1) { m2 = m1; m1 = v; }
            else if (v > m2) { m2 = v; }
        }
#pragma unroll
        for (int off = 1; off <= 2; off <<= 1) {
            float o1 = __shfl_xor_sync(0xffffffffu, m1, off);
            float o2 = __shfl_xor_sync(0xffffffffu, m2, off);
            if (o1 > m1) { m2 = fmaxf(m1, o2); m1 = o1; }
            else         { m2 = fmaxf(m2, o1); }
        }
        const float gsc = m1 + m2;
        const int myg = lane >> 2;

        int rank = 0;
#pragma unroll
        for (int g2 = 0; g2 < N_GROUPS; ++g2) {
            float og = __shfl_sync(0xffffffffu, gsc, g2 * 4);
            rank += (og > gsc) || (og == gsc && g2 < myg);
        }
        const bool kept = rank < TOPK_GROUPS;

        uint32_t key[8];
#pragma unroll
        for (int j = 0; j < 8; ++j) key[j] = fkey(b[j]);
        uint32_t mask = kept ? 0xFFu : 0u;

        float topw[TOPK]; int topi[TOPK];
        float wsum = 0.f;
#pragma unroll
        for (int it = 0; it < TOPK; ++it) {
            uint32_t bk = 0; uint32_t be = 0x7fffffffu; float bs = 0.f;
#pragma unroll
            for (int j = 0; j < 8; ++j) {
                const bool live = (mask >> j) & 1u;
                if (live && key[j] > bk) { bk = key[j]; be = lane * 8 + j; bs = s[j]; }
            }
#pragma unroll
            for (int off = 16; off; off >>= 1) {
                uint32_t ok = __shfl_xor_sync(0xffffffffu, bk, off);
                uint32_t oe = __shfl_xor_sync(0xffffffffu, be, off);
                float    os = __shfl_xor_sync(0xffffffffu, bs, off);
                if (ok > bk || (ok == bk && oe < be)) { bk = ok; be = oe; bs = os; }
            }
            topw[it] = bs; topi[it] = (int)be; wsum += bs;
            if ((be >> 3) == (uint32_t)lane) mask &= ~(1u << (be & 7u));
        }

        const float scale = ROUTE_SCALE / fmaxf(wsum, 1e-10f);
        if (lane == 0) {
            const size_t t = (size_t)mt_blk * 64 + row;
#pragma unroll
            for (int j = 0; j < TOPK; ++j) {
                out_w[t * TOPK + j] = topw[j] * scale;
                out_i[t * TOPK + j] = (float)topi[j];
            }
        }
    }
}

// ---------------------------------------------------------------------------
extern "C" void kernel_launch(void* const* d_in, const int* in_sizes, int n_in,
                              void* d_out, int out_size)
{
    const float* x    = (const float*)d_in[0];
    const float* w    = (const float*)d_in[1];
    const float* bias = (const float*)d_in[2];

    int T = in_sizes[0] / DIM_K;
    if (T > MAX_T) T = MAX_T;

    float* out_w = (float*)d_out;
    float* out_i = (float*)d_out + (size_t)T * TOPK;

    wsplit_kernel<<<1024, 256>>>(w);

    cudaFuncSetAttribute(fused_kernel,
                         cudaFuncAttributeMaxDynamicSharedMemorySize, SMEM_BYTES);
    fused_kernel<<<T / 64, 256, SMEM_BYTES>>>(x, bias, out_w, out_i);
}

// round 11
// speedup vs baseline: 1.1437x; 1.0473x over previous
#include <cuda_runtime.h>
#include <cuda_fp16.h>
#include <math.h>
#include <stdint.h>

// ---------------------------------------------------------------------------
// AuxLossFreeGate, fused GEMM+gate, 16-warp CTA:
//   CTA = 64 tokens x 256 experts, 512 threads, warp grid 4(M) x 4(N),
//   warp tile 16 tokens x 64 experts. fp16 mma.sync, 2-way RN split
//   (v = v1 + v2*2^-12), 3 product planes. B via cp.async from pre-split
//   W image; A LDG+split+STS inline. Gate runs in-CTA from SMEM scores.
// ---------------------------------------------------------------------------

#define N_EXPERTS   256
#define DIM_K       2048
#define N_GROUPS    8
#define TOPK        8
#define TOPK_GROUPS 4
#define ROUTE_SCALE 2.5f
#define MAX_T       32768
#define NEG_INF_F   (-1e30f)

// ---------------- GEMM config ----------------
#define KC       32
#define NCHUNK   (DIM_K / KC)
#define ABLK     144
#define APLANE   (8 * ABLK)               // 1152 u32 per A plane (64 rows)
#define BBLK     66
#define BPLANE   (64 * BBLK)              // 4224 u32 per B plane (256 experts)
#define SB_OFF   (2 * APLANE)             // 2304
#define BCHUNK   (2 * BPLANE)             // 8448 u32 per chunk in W image
#define SMEM_U32 (SB_OFF + BCHUNK)        // 10752 u32 per buffer
#define SC_OFF   (2 * SMEM_U32)           // scores region after both buffers
#define SC_STRIDE 264                     // floats per score row
#define SMEM_BYTES ((SC_OFF + 64 * SC_STRIDE) * 4)   // 153600 B

#define NTHREADS 512

// W image: [chunk(64)][plane(2)][4224], exact SMEM B layout.
__device__ __align__(16) uint32_t g_wimg[NCHUNK * BCHUNK];

#define MMA_F16(d, a, b) asm volatile( \
    "mma.sync.aligned.m16n8k16.row.col.f32.f16.f16.f32 " \
    "{%0,%1,%2,%3},{%4,%5,%6,%7},{%8,%9},{%0,%1,%2,%3};" \
    : "+f"((d)[0]), "+f"((d)[1]), "+f"((d)[2]), "+f"((d)[3]) \
    : "r"((a).x), "r"((a).y), "r"((a).z), "r"((a).w), "r"((b).x), "r"((b).y))

#define CP_ASYNC16(dst_u32, src_ptr) \
    asm volatile("cp.async.cg.shared.global [%0], [%1], 16;" \
                 :: "r"(dst_u32), "l"(src_ptr) : "memory")
#define CP_COMMIT()  asm volatile("cp.async.commit_group;" ::: "memory")
#define CP_WAIT0()   asm volatile("cp.async.wait_group 0;" ::: "memory")

__device__ __forceinline__ uint32_t smem_to_u32(const void* p) {
    uint32_t a;
    asm("{ .reg .u64 t; cvta.to.shared.u64 t, %1; cvt.u32.u64 %0, t; }" : "=r"(a) : "l"(p));
    return a;
}

// 2-way fp16 split of 4 floats, pairwise packed (even k in lo half).
__device__ __forceinline__ void hsplit4(float4 v, uint32_t p1[2], uint32_t p2[2])
{
    __half2 a1 = __floats2half2_rn(v.x, v.y);
    __half2 b1 = __floats2half2_rn(v.z, v.w);
    p1[0] = *(uint32_t*)&a1;
    p1[1] = *(uint32_t*)&b1;
    float rx = (v.x - __half2float(__low2half(a1)))  * 4096.0f;
    float ry = (v.y - __half2float(__high2half(a1))) * 4096.0f;
    float rz = (v.z - __half2float(__low2half(b1)))  * 4096.0f;
    float rw = (v.w - __half2float(__high2half(b1))) * 4096.0f;
    __half2 a2 = __floats2half2_rn(rx, ry);
    __half2 b2 = __floats2half2_rn(rz, rw);
    p2[0] = *(uint32_t*)&a2;
    p2[1] = *(uint32_t*)&b2;
}

__device__ __forceinline__ float sigf(float v) { return 1.0f / (1.0f + expf(-v)); }

__device__ __forceinline__ uint32_t fkey(float f) {
    uint32_t u = __float_as_uint(f);
    return u ^ (uint32_t)(((int32_t)u >> 31) | 0x80000000);
}

// ---------------------------------------------------------------------------
// Kernel 0: pre-split W into fragment-image layout (validated rounds 7-10).
// ---------------------------------------------------------------------------
__global__ __launch_bounds__(256)
void wsplit_kernel(const float* __restrict__ W)
{
    const int gid = blockIdx.x * 256 + threadIdx.x;   // 0..262143
    const int n = gid >> 10;                          // expert 0..255
    const int p = gid & 1023;                         // k-pair
    const int k = 2 * p;

    float2 w = *(const float2*)(W + (size_t)n * DIM_K + k);
    uint32_t p1[2], p2[2];
    hsplit4(make_float4(w.x, w.y, 0.f, 0.f), p1, p2);

    const int nt = n >> 3;
    const int cn = n & 7;
    const int c  = k >> 5;
    const int kk = k & 31;
    const int ks = kk >> 4;
    const int kb = kk & 15;
    const int slot = cn * 4 + ((kb >> 1) & 3);
    const int reg  = kb >> 3;

    const int base = c * BCHUNK + (nt * 2 + ks) * BBLK + slot * 2 + reg;
    g_wimg[base]          = p1[0];
    g_wimg[base + BPLANE] = p2[0];
}

// ---------------------------------------------------------------------------
// Kernel 1: fused GEMM + gate. 512 threads, 16 warps (4M x 4N).
// ---------------------------------------------------------------------------
__global__ __launch_bounds__(NTHREADS)
void fused_kernel(const float* __restrict__ X, const float* __restrict__ bias,
                  float* __restrict__ out_w, float* __restrict__ out_i)
{
    extern __shared__ uint32_t sm[];
    const uint32_t smem_base = smem_to_u32(sm);
    const int tid  = threadIdx.x;
    const int warp = tid >> 5;
    const int lane = tid & 31;

    const int mt_blk = blockIdx.x;                  // 64-token tile
    const float* xb = X + (size_t)mt_blk * 64 * DIM_K;

    // A loader geometry: 512 float4 per chunk, exactly 1 per thread
    int goff, aad;
    {
        const int row = tid >> 3;                   // 0..63
        const int c4  = (tid & 7) * 4;
        goff = row * DIM_K + c4;
        const int ks = c4 >> 4;
        const int kb = c4 & 15;
        const int tc = (kb >> 1) & 3;
        const int mt = row >> 4, r = row & 15;
        const int slot = (r & 7) * 4 + tc;
        const int reg  = (r >> 3) + 2 * ((kb >> 3) & 1);
        aad = (mt * 2 + ks) * ABLK + slot * 4 + (slot >> 3) * 4 + reg;
    }

    float accM[8][4], accS[8][4];
#pragma unroll
    for (int ni = 0; ni < 8; ++ni)
#pragma unroll
        for (int q = 0; q < 4; ++q) { accM[ni][q] = 0.f; accS[ni][q] = 0.f; }

    const int wm  = warp >> 2;                      // m-tile 0..3 (16 rows)
    const int wnt = (warp & 3) * 8;                 // n-tile base (8 tiles of 8)

    // ---- prologue: issue B(0) cp.async, load A(0) register ----
    {
        const uint32_t dstb = smem_base + SB_OFF * 4;
#pragma unroll
        for (int j = 0; j < 4; ++j) {
            const int idx = j * 512 + tid;          // 0..2047 uint4
            CP_ASYNC16(dstb + idx * 16, g_wimg + idx * 4);
        }
        if (tid < 64) {
            const int idx = 2048 + tid;
            CP_ASYNC16(dstb + idx * 16, g_wimg + idx * 4);
        }
        CP_COMMIT();
    }
    float4 ra = *(const float4*)(xb + goff);

    for (int c = 0; c < NCHUNK; ++c) {
        uint32_t* smb = sm + (c & 1) * SMEM_U32;

        // ---- split + store A(c) ----
        {
            uint32_t p1[2], p2[2];
            hsplit4(ra, p1, p2);
            smb[aad]              = p1[0];
            smb[aad + 4]          = p1[1];
            smb[aad + APLANE]     = p2[0];
            smb[aad + APLANE + 4] = p2[1];
        }

        CP_WAIT0();                                  // B(c) landed
        __syncthreads();

        // ---- issue B(c+1) into the other buffer ----
        if (c + 1 < NCHUNK) {
            const uint32_t* src = g_wimg + (c + 1) * BCHUNK;
            const uint32_t dstb = smem_base + (((c + 1) & 1) * SMEM_U32 + SB_OFF) * 4;
#pragma unroll
            for (int j = 0; j < 4; ++j) {
                const int idx = j * 512 + tid;
                CP_ASYNC16(dstb + idx * 16, src + idx * 4);
            }
            if (tid < 64) {
                const int idx = 2048 + tid;
                CP_ASYNC16(dstb + idx * 16, src + idx * 4);
            }
        }
        CP_COMMIT();

        // ---- prefetch A(c+1) ----
        if (c + 1 < NCHUNK) {
            const int k0 = (c + 1) * KC;
            ra = *(const float4*)(xb + goff + k0);
        }

        // ---- compute chunk c: 3 planes ----
#pragma unroll
        for (int ks = 0; ks < 2; ++ks) {
            uint4 af[2];
#pragma unroll
            for (int p = 0; p < 2; ++p)
                af[p] = *(const uint4*)&smb[p * APLANE +
                    (wm * 2 + ks) * ABLK + lane * 4 + (lane >> 3) * 4];

#pragma unroll
            for (int nq = 0; nq < 2; ++nq) {
                const int nb = nq * 4;
                uint2 bf[4][2];
#pragma unroll
                for (int ni4 = 0; ni4 < 4; ++ni4) {
                    const int bbase = ((wnt + nb + ni4) * 2 + ks) * BBLK + lane * 2;
#pragma unroll
                    for (int q = 0; q < 2; ++q)
                        bf[ni4][q] = *(const uint2*)&smb[SB_OFF + q * BPLANE + bbase];
                }
#pragma unroll
                for (int ni4 = 0; ni4 < 4; ++ni4)
                    MMA_F16(accM[nb + ni4], af[0], bf[ni4][0]);
#pragma unroll
                for (int ni4 = 0; ni4 < 4; ++ni4)
                    MMA_F16(accS[nb + ni4], af[0], bf[ni4][1]);
#pragma unroll
                for (int ni4 = 0; ni4 < 4; ++ni4)
                    MMA_F16(accS[nb + ni4], af[1], bf[ni4][0]);
            }
        }
    }

    // ---- epilogue 1: sigmoid scores -> SMEM (64 x 256, stride 264) ----
    __syncthreads();
    float* scs = (float*)(sm + SC_OFF);
    const float INV = 1.0f / 4096.0f;
    const int rbase = wm * 16 + (lane >> 2);
    const int cbase = (warp & 3) * 64 + (lane & 3) * 2;
#pragma unroll
    for (int ni = 0; ni < 8; ++ni) {
        const int cc = cbase + ni * 8;
        float2 v0, v1;
        v0.x = sigf(fmaf(accS[ni][0], INV, accM[ni][0]));
        v0.y = sigf(fmaf(accS[ni][1], INV, accM[ni][1]));
        v1.x = sigf(fmaf(accS[ni][2], INV, accM[ni][2]));
        v1.y = sigf(fmaf(accS[ni][3], INV, accM[ni][3]));
        *(float2*)&scs[rbase * SC_STRIDE + cc] = v0;
        *(float2*)&scs[(rbase + 8) * SC_STRIDE + cc] = v1;
    }
    __syncthreads();

    // ---- epilogue 2: gate 4 tokens per warp ----
    float4 bb0 = *(const float4*)(bias + lane * 8);
    float4 bb1 = *(const float4*)(bias + lane * 8 + 4);

    for (int tt = 0; tt < 4; ++tt) {
        const int row = warp * 4 + tt;
        const float* srow = scs + row * SC_STRIDE;

        float s[8], b[8];
        {
            float4 s0 = *(const float4*)(srow + lane * 8);
            float4 s1 = *(const float4*)(srow + lane * 8 + 4);
            s[0]=s0.x; s[1]=s0.y; s[2]=s0.z; s[3]=s0.w;
            s[4]=s1.x; s[5]=s1.y; s[6]=s1.z; s[7]=s1.w;
            b[0]=s[0]+bb0.x; b[1]=s[1]+bb0.y; b[2]=s[2]+bb0.z; b[3]=s[3]+bb0.w;
            b[4]=s[4]+bb1.x; b[5]=s[5]+bb1.y; b[6]=s[6]+bb1.z; b[7]=s[7]+bb1.w;
        }

        float m1 = NEG_INF_F, m2 = NEG_INF_F;
#pragma unroll
        for (int j = 0; j < 8; ++j) {
            float v = b[j];
            if (v > m1) { m2 = m1; m1 = v; }
            else if (v > m2) { m2 = v; }
        }
#pragma unroll
        for (int off = 1; off <= 2; off <<= 1) {
            float o1 = __shfl_xor_sync(0xffffffffu, m1, off);
            float o2 = __shfl_xor_sync(0xffffffffu, m2, off);
            if (o1 > m1) { m2 = fmaxf(m1, o2); m1 = o1; }
            else         { m2 = fmaxf(m2, o1); }
        }
        const float gsc = m1 + m2;
        const int myg = lane >> 2;

        int rank = 0;
#pragma unroll
        for (int g2 = 0; g2 < N_GROUPS; ++g2) {
            float og = __shfl_sync(0xffffffffu, gsc, g2 * 4);
            rank += (og > gsc) || (og == gsc && g2 < myg);
        }
        const bool kept = rank < TOPK_GROUPS;

        uint32_t key[8];
#pragma unroll
        for (int j = 0; j < 8; ++j) key[j] = fkey(b[j]);
        uint32_t mask = kept ? 0xFFu : 0u;

        float topw[TOPK]; int topi[TOPK];
        float wsum = 0.f;
#pragma unroll
        for (int it = 0; it < TOPK; ++it) {
            uint32_t bk = 0; uint32_t be = 0x7fffffffu; float bs = 0.f;
#pragma unroll
            for (int j = 0; j < 8; ++j) {
                const bool live = (mask >> j) & 1u;
                if (live && key[j] > bk) { bk = key[j]; be = lane * 8 + j; bs = s[j]; }
            }
#pragma unroll
            for (int off = 16; off; off >>= 1) {
                uint32_t ok = __shfl_xor_sync(0xffffffffu, bk, off);
                uint32_t oe = __shfl_xor_sync(0xffffffffu, be, off);
                float    os = __shfl_xor_sync(0xffffffffu, bs, off);
                if (ok > bk || (ok == bk && oe < be)) { bk = ok; be = oe; bs = os; }
            }
            topw[it] = bs; topi[it] = (int)be; wsum += bs;
            if ((be >> 3) == (uint32_t)lane) mask &= ~(1u << (be & 7u));
        }

        const float scale = ROUTE_SCALE / fmaxf(wsum, 1e-10f);
        if (lane == 0) {
            const size_t t = (size_t)mt_blk * 64 + row;
#pragma unroll
            for (int j = 0; j < TOPK; ++j) {
                out_w[t * TOPK + j] = topw[j] * scale;
                out_i[t * TOPK + j] = (float)topi[j];
            }
        }
    }
}

// ---------------------------------------------------------------------------
extern "C" void kernel_launch(void* const* d_in, const int* in_sizes, int n_in,
                              void* d_out, int out_size)
{
    const float* x    = (const float*)d_in[0];
    const float* w    = (const float*)d_in[1];
    const float* bias = (const float*)d_in[2];

    int T = in_sizes[0] / DIM_K;
    if (T > MAX_T) T = MAX_T;

    float* out_w = (float*)d_out;
    float* out_i = (float*)d_out + (size_t)T * TOPK;

    wsplit_kernel<<<1024, 256>>>(w);

    cudaFuncSetAttribute(fused_kernel,
                         cudaFuncAttributeMaxDynamicSharedMemorySize, SMEM_BYTES);
    fused_kernel<<<T / 64, NTHREADS, SMEM_BYTES>>>(x, bias, out_w, out_i);
}

// round 12
// speedup vs baseline: 1.3525x; 1.1826x over previous
#include <cuda_runtime.h>
#include <cuda_fp16.h>
#include <math.h>
#include <stdint.h>

// ---------------------------------------------------------------------------
// AuxLossFreeGate, fused GEMM+gate, 2-CTA/SM design:
//   CTA = 32 tokens x 256 experts, 256 threads (8 warps, 1Mx8N groups of
//   32x32 warp tiles -> 2 m-tiles x 4 n-tiles per warp).
//   fp16 mma.sync, 2-way RN split (v = v1 + v2*2^-12), 3 product planes.
//   B via cp.async from pre-split W image; A LDG+split+STS inline.
//   Scores SMEM region OVERLAYS the (dead) GEMM buffers -> 75 KB SMEM,
//   so TWO CTAs co-reside per SM and overlap each other's barrier bubbles.
// ---------------------------------------------------------------------------

#define N_EXPERTS   256
#define DIM_K       2048
#define N_GROUPS    8
#define TOPK        8
#define TOPK_GROUPS 4
#define ROUTE_SCALE 2.5f
#define MAX_T       32768
#define NEG_INF_F   (-1e30f)

// ---------------- GEMM config ----------------
#define KC       32
#define NCHUNK   (DIM_K / KC)
#define ABLK     144
#define APLANE   (4 * ABLK)               // 576 u32 per A plane (32 rows)
#define BBLK     66
#define BPLANE   (64 * BBLK)              // 4224 u32 per B plane (256 experts)
#define SB_OFF   (2 * APLANE)             // 1152
#define BCHUNK   (2 * BPLANE)             // 8448 u32 per chunk in W image
#define SMEM_U32 (SB_OFF + BCHUNK)        // 9600 u32 per buffer
#define SC_STRIDE 264                     // floats per score row
#define SMEM_BYTES (2 * SMEM_U32 * 4)     // 76800 B (scores overlay buffer 0+)

#define NTHREADS 256

// W image: [chunk(64)][plane(2)][4224], exact SMEM B layout.
__device__ __align__(16) uint32_t g_wimg[NCHUNK * BCHUNK];

#define MMA_F16(d, a, b) asm volatile( \
    "mma.sync.aligned.m16n8k16.row.col.f32.f16.f16.f32 " \
    "{%0,%1,%2,%3},{%4,%5,%6,%7},{%8,%9},{%0,%1,%2,%3};" \
    : "+f"((d)[0]), "+f"((d)[1]), "+f"((d)[2]), "+f"((d)[3]) \
    : "r"((a).x), "r"((a).y), "r"((a).z), "r"((a).w), "r"((b).x), "r"((b).y))

#define CP_ASYNC16(dst_u32, src_ptr) \
    asm volatile("cp.async.cg.shared.global [%0], [%1], 16;" \
                 :: "r"(dst_u32), "l"(src_ptr) : "memory")
#define CP_COMMIT()  asm volatile("cp.async.commit_group;" ::: "memory")
#define CP_WAIT0()   asm volatile("cp.async.wait_group 0;" ::: "memory")

__device__ __forceinline__ uint32_t smem_to_u32(const void* p) {
    uint32_t a;
    asm("{ .reg .u64 t; cvta.to.shared.u64 t, %1; cvt.u32.u64 %0, t; }" : "=r"(a) : "l"(p));
    return a;
}

// 2-way fp16 split of 4 floats, pairwise packed (even k in lo half).
__device__ __forceinline__ void hsplit4(float4 v, uint32_t p1[2], uint32_t p2[2])
{
    __half2 a1 = __floats2half2_rn(v.x, v.y);
    __half2 b1 = __floats2half2_rn(v.z, v.w);
    p1[0] = *(uint32_t*)&a1;
    p1[1] = *(uint32_t*)&b1;
    float rx = (v.x - __half2float(__low2half(a1)))  * 4096.0f;
    float ry = (v.y - __half2float(__high2half(a1))) * 4096.0f;
    float rz = (v.z - __half2float(__low2half(b1)))  * 4096.0f;
    float rw = (v.w - __half2float(__high2half(b1))) * 4096.0f;
    __half2 a2 = __floats2half2_rn(rx, ry);
    __half2 b2 = __floats2half2_rn(rz, rw);
    p2[0] = *(uint32_t*)&a2;
    p2[1] = *(uint32_t*)&b2;
}

__device__ __forceinline__ float sigf(float v) { return 1.0f / (1.0f + expf(-v)); }

__device__ __forceinline__ uint32_t fkey(float f) {
    uint32_t u = __float_as_uint(f);
    return u ^ (uint32_t)(((int32_t)u >> 31) | 0x80000000);
}

// ---------------------------------------------------------------------------
// Kernel 0: pre-split W into fragment-image layout (validated rounds 7-11).
// ---------------------------------------------------------------------------
__global__ __launch_bounds__(256)
void wsplit_kernel(const float* __restrict__ W)
{
    const int gid = blockIdx.x * 256 + threadIdx.x;   // 0..262143
    const int n = gid >> 10;                          // expert 0..255
    const int p = gid & 1023;                         // k-pair
    const int k = 2 * p;

    float2 w = *(const float2*)(W + (size_t)n * DIM_K + k);
    uint32_t p1[2], p2[2];
    hsplit4(make_float4(w.x, w.y, 0.f, 0.f), p1, p2);

    const int nt = n >> 3;
    const int cn = n & 7;
    const int c  = k >> 5;
    const int kk = k & 31;
    const int ks = kk >> 4;
    const int kb = kk & 15;
    const int slot = cn * 4 + ((kb >> 1) & 3);
    const int reg  = kb >> 3;

    const int base = c * BCHUNK + (nt * 2 + ks) * BBLK + slot * 2 + reg;
    g_wimg[base]          = p1[0];
    g_wimg[base + BPLANE] = p2[0];
}

// ---------------------------------------------------------------------------
// Kernel 1: fused GEMM + gate. 256 threads, 8 warps, warp tile 32x32.
// ---------------------------------------------------------------------------
__global__ __launch_bounds__(NTHREADS, 2)
void fused_kernel(const float* __restrict__ X, const float* __restrict__ bias,
                  float* __restrict__ out_w, float* __restrict__ out_i)
{
    extern __shared__ uint32_t sm[];
    const uint32_t smem_base = smem_to_u32(sm);
    const int tid  = threadIdx.x;
    const int warp = tid >> 5;
    const int lane = tid & 31;

    const int mt_blk = blockIdx.x;                  // 32-token tile
    const float* xb = X + (size_t)mt_blk * 32 * DIM_K;

    // A loader geometry: 256 float4 per chunk, exactly 1 per thread
    int goff, aad;
    {
        const int row = tid >> 3;                   // 0..31
        const int c4  = (tid & 7) * 4;
        goff = row * DIM_K + c4;
        const int ks = c4 >> 4;
        const int kb = c4 & 15;
        const int tc = (kb >> 1) & 3;
        const int mt = row >> 4, r = row & 15;      // m-tile 0..1
        const int slot = (r & 7) * 4 + tc;
        const int reg  = (r >> 3) + 2 * ((kb >> 3) & 1);
        aad = (mt * 2 + ks) * ABLK + slot * 4 + (slot >> 3) * 4 + reg;
    }

    float accM[2][4][4], accS[2][4][4];
#pragma unroll
    for (int mi = 0; mi < 2; ++mi)
#pragma unroll
        for (int ni = 0; ni < 4; ++ni)
#pragma unroll
            for (int q = 0; q < 4; ++q) { accM[mi][ni][q] = 0.f; accS[mi][ni][q] = 0.f; }

    // warp covers all 32 token rows (m-tiles 0,1) x 32 experts (n-tiles warp*4..+3)
    const int wnt = warp * 4;

    // ---- prologue: issue B(0) cp.async, load A(0) register ----
    {
        const uint32_t dstb = smem_base + SB_OFF * 4;
#pragma unroll
        for (int j = 0; j < 8; ++j) {
            const int idx = j * 256 + tid;          // 0..2047 uint4
            CP_ASYNC16(dstb + idx * 16, g_wimg + idx * 4);
        }
        if (tid < 64) {
            const int idx = 2048 + tid;
            CP_ASYNC16(dstb + idx * 16, g_wimg + idx * 4);
        }
        CP_COMMIT();
    }
    float4 ra = *(const float4*)(xb + goff);

    for (int c = 0; c < NCHUNK; ++c) {
        uint32_t* smb = sm + (c & 1) * SMEM_U32;

        // ---- split + store A(c) ----
        {
            uint32_t p1[2], p2[2];
            hsplit4(ra, p1, p2);
            smb[aad]              = p1[0];
            smb[aad + 4]          = p1[1];
            smb[aad + APLANE]     = p2[0];
            smb[aad + APLANE + 4] = p2[1];
        }

        CP_WAIT0();                                  // B(c) landed
        __syncthreads();

        // ---- issue B(c+1) into the other buffer ----
        if (c + 1 < NCHUNK) {
            const uint32_t* src = g_wimg + (c + 1) * BCHUNK;
            const uint32_t dstb = smem_base + (((c + 1) & 1) * SMEM_U32 + SB_OFF) * 4;
#pragma unroll
            for (int j = 0; j < 8; ++j) {
                const int idx = j * 256 + tid;
                CP_ASYNC16(dstb + idx * 16, src + idx * 4);
            }
            if (tid < 64) {
                const int idx = 2048 + tid;
                CP_ASYNC16(dstb + idx * 16, src + idx * 4);
            }
        }
        CP_COMMIT();

        // ---- prefetch A(c+1) ----
        if (c + 1 < NCHUNK) {
            const int k0 = (c + 1) * KC;
            ra = *(const float4*)(xb + goff + k0);
        }

        // ---- compute chunk c: 3 planes, warp tile 32x32 ----
#pragma unroll
        for (int ks = 0; ks < 2; ++ks) {
            uint4 af[2][2];                          // [plane][m-tile]
#pragma unroll
            for (int p = 0; p < 2; ++p)
#pragma unroll
                for (int mi = 0; mi < 2; ++mi)
                    af[p][mi] = *(const uint4*)&smb[p * APLANE +
                        (mi * 2 + ks) * ABLK + lane * 4 + (lane >> 3) * 4];

            uint2 bf[4][2];                          // [n-tile][plane]
#pragma unroll
            for (int ni = 0; ni < 4; ++ni) {
                const int bbase = ((wnt + ni) * 2 + ks) * BBLK + lane * 2;
#pragma unroll
                for (int q = 0; q < 2; ++q)
                    bf[ni][q] = *(const uint2*)&smb[SB_OFF + q * BPLANE + bbase];
            }
#pragma unroll
            for (int mi = 0; mi < 2; ++mi)
#pragma unroll
                for (int ni = 0; ni < 4; ++ni)
                    MMA_F16(accM[mi][ni], af[0][mi], bf[ni][0]);
#pragma unroll
            for (int mi = 0; mi < 2; ++mi)
#pragma unroll
                for (int ni = 0; ni < 4; ++ni)
                    MMA_F16(accS[mi][ni], af[0][mi], bf[ni][1]);
#pragma unroll
            for (int mi = 0; mi < 2; ++mi)
#pragma unroll
                for (int ni = 0; ni < 4; ++ni)
                    MMA_F16(accS[mi][ni], af[1][mi], bf[ni][0]);
        }
    }

    // ---- epilogue 1: sigmoid scores -> SMEM overlay (32 x 256, stride 264) --
    __syncthreads();                                 // buffers dead, overlay OK
    float* scs = (float*)sm;
    const float INV = 1.0f / 4096.0f;
    const int rbase = lane >> 2;
    const int cbase = warp * 32 + (lane & 3) * 2;
#pragma unroll
    for (int mi = 0; mi < 2; ++mi) {
#pragma unroll
        for (int ni = 0; ni < 4; ++ni) {
            const int rr = rbase + mi * 16;
            const int cc = cbase + ni * 8;
            float2 v0, v1;
            v0.x = sigf(fmaf(accS[mi][ni][0], INV, accM[mi][ni][0]));
            v0.y = sigf(fmaf(accS[mi][ni][1], INV, accM[mi][ni][1]));
            v1.x = sigf(fmaf(accS[mi][ni][2], INV, accM[mi][ni][2]));
            v1.y = sigf(fmaf(accS[mi][ni][3], INV, accM[mi][ni][3]));
            *(float2*)&scs[rr * SC_STRIDE + cc] = v0;
            *(float2*)&scs[(rr + 8) * SC_STRIDE + cc] = v1;
        }
    }
    __syncthreads();

    // ---- epilogue 2: gate 4 tokens per warp (validated logic) ----
    float4 bb0 = *(const float4*)(bias + lane * 8);
    float4 bb1 = *(const float4*)(bias + lane * 8 + 4);

    for (int tt = 0; tt < 4; ++tt) {
        const int row = warp * 4 + tt;
        const float* srow = scs + row * SC_STRIDE;

        float s[8], b[8];
        {
            float4 s0 = *(const float4*)(srow + lane * 8);
            float4 s1 = *(const float4*)(srow + lane * 8 + 4);
            s[0]=s0.x; s[1]=s0.y; s[2]=s0.z; s[3]=s0.w;
            s[4]=s1.x; s[5]=s1.y; s[6]=s1.z; s[7]=s1.w;
            b[0]=s[0]+bb0.x; b[1]=s[1]+bb0.y; b[2]=s[2]+bb0.z; b[3]=s[3]+bb0.w;
            b[4]=s[4]+bb1.x; b[5]=s[5]+bb1.y; b[6]=s[6]+bb1.z; b[7]=s[7]+bb1.w;
        }

        float m1 = NEG_INF_F, m2 = NEG_INF_F;
#pragma unroll
        for (int j = 0; j < 8; ++j) {
            float v = b[j];
            if (v > m1) { m2 = m1; m1 = v; }
            else if (v > m2) { m2 = v; }
        }
#pragma unroll
        for (int off = 1; off <= 2; off <<= 1) {
            float o1 = __shfl_xor_sync(0xffffffffu, m1, off);
            float o2 = __shfl_xor_sync(0xffffffffu, m2, off);
            if (o1 > m1) { m2 = fmaxf(m1, o2); m1 = o1; }
            else         { m2 = fmaxf(m2, o1); }
        }
        const float gsc = m1 + m2;
        const int myg = lane >> 2;

        int rank = 0;
#pragma unroll
        for (int g2 = 0; g2 < N_GROUPS; ++g2) {
            float og = __shfl_sync(0xffffffffu, gsc, g2 * 4);
            rank += (og > gsc) || (og == gsc && g2 < myg);
        }
        const bool kept = rank < TOPK_GROUPS;

        uint32_t key[8];
#pragma unroll
        for (int j = 0; j < 8; ++j) key[j] = fkey(b[j]);
        uint32_t mask = kept ? 0xFFu : 0u;

        float topw[TOPK]; int topi[TOPK];
        float wsum = 0.f;
#pragma unroll
        for (int it = 0; it < TOPK; ++it) {
            uint32_t bk = 0; uint32_t be = 0x7fffffffu; float bs = 0.f;
#pragma unroll
            for (int j = 0; j < 8; ++j) {
                const bool live = (mask >> j) & 1u;
                if (live && key[j] > bk) { bk = key[j]; be = lane * 8 + j; bs = s[j]; }
            }
#pragma unroll
            for (int off = 16; off; off >>= 1) {
                uint32_t ok = __shfl_xor_sync(0xffffffffu, bk, off);
                uint32_t oe = __shfl_xor_sync(0xffffffffu, be, off);
                float    os = __shfl_xor_sync(0xffffffffu, bs, off);
                if (ok > bk || (ok == bk && oe < be)) { bk = ok; be = oe; bs = os; }
            }
            topw[it] = bs; topi[it] = (int)be; wsum += bs;
            if ((be >> 3) == (uint32_t)lane) mask &= ~(1u << (be & 7u));
        }

        const float scale = ROUTE_SCALE / fmaxf(wsum, 1e-10f);
        if (lane == 0) {
            const size_t t = (size_t)mt_blk * 32 + row;
#pragma unroll
            for (int j = 0; j < TOPK; ++j) {
                out_w[t * TOPK + j] = topw[j] * scale;
                out_i[t * TOPK + j] = (float)topi[j];
            }
        }
    }
}

// ---------------------------------------------------------------------------
extern "C" void kernel_launch(void* const* d_in, const int* in_sizes, int n_in,
                              void* d_out, int out_size)
{
    const float* x    = (const float*)d_in[0];
    const float* w    = (const float*)d_in[1];
    const float* bias = (const float*)d_in[2];

    int T = in_sizes[0] / DIM_K;
    if (T > MAX_T) T = MAX_T;

    float* out_w = (float*)d_out;
    float* out_i = (float*)d_out + (size_t)T * TOPK;

    wsplit_kernel<<<1024, 256>>>(w);

    cudaFuncSetAttribute(fused_kernel,
                         cudaFuncAttributeMaxDynamicSharedMemorySize, SMEM_BYTES);
    fused_kernel<<<T / 32, NTHREADS, SMEM_BYTES>>>(x, bias, out_w, out_i);
}